// round 14
// baseline (speedup 1.0000x reference)
#include <cuda_runtime.h>
#include <cuda_fp16.h>
#include <cstdint>

// Problem constants: B=8192, T=2048, H=5, input dim 1.
#define MAX_B 8192
#define MAX_T 2048
#define HID 5

typedef unsigned long long ull;

// Packed x: xP[t/8][b][8] -> 32B per sequence per 8 steps, coalesced.
__device__ float g_xP[(size_t)MAX_T * MAX_B];

__device__ __forceinline__ float fast_tanh(float x) {
    float r;
    asm("tanh.approx.f32 %0, %1;" : "=f"(r) : "f"(x));
    return r;
}
// Packed half2 tanh: one MUFU op, two tanhs.
__device__ __forceinline__ uint32_t tanh_h2(uint32_t x) {
    uint32_t r;
    asm("tanh.approx.f16x2 %0, %1;" : "=r"(r) : "r"(x));
    return r;
}
// Pack two f32 into f16x2: hi half = first operand, lo half = second.
__device__ __forceinline__ uint32_t cvt_h2(float hi, float lo) {
    uint32_t r;
    asm("cvt.rn.f16x2.f32 %0, %1, %2;" : "=r"(r) : "f"(hi), "f"(lo));
    return r;
}
__device__ __forceinline__ ull pk2(float lo, float hi) {
    ull r;
    asm("mov.b64 %0, {%1, %2};" : "=l"(r) : "f"(lo), "f"(hi));
    return r;
}
__device__ __forceinline__ void upk2(ull v, float& lo, float& hi) {
    asm("mov.b64 {%0, %1}, %2;" : "=f"(lo), "=f"(hi) : "l"(v));
}
// Packed fp32x2 FMA (sm_100+): one instruction = 2 fp32 FMAs.
__device__ __forceinline__ ull fma2(ull a, ull b, ull c) {
    ull r;
    asm("fma.rn.f32x2 %0, %1, %2, %3;" : "=l"(r) : "l"(a), "l"(b), "l"(c));
    return r;
}
__device__ __forceinline__ __half2 u2h2(uint32_t v) {
    __half2 h;
    *reinterpret_cast<uint32_t*>(&h) = v;
    return h;
}

// ---------------- pack: x[B,T] -> xP[T/8][B][8] ----------------
__global__ void pack_kernel(const float* __restrict__ x, int B, int T) {
    const int nblk = T / 8;
    int idx = blockIdx.x * blockDim.x + threadIdx.x;   // over B * nblk
    if (idx >= B * nblk) return;
    int b = idx / nblk;
    int k = idx - b * nblk;
    const float4* src = reinterpret_cast<const float4*>(x + (size_t)b * T + (size_t)k * 8);
    float4 u = src[0];
    float4 v = src[1];
    float4* dst = reinterpret_cast<float4*>(g_xP + ((size_t)k * B + b) * 8);
    dst[0] = u;
    dst[1] = v;
}

// ---------------- LSTM: 5 lanes/seq, lane = hidden unit, f16x2 gates ------
// Warp = 6 groups of 5 lanes (lanes 30,31 junk-compute a clamped seq).
// Lane (group g, role j) owns unit j completely. Gate tanhs: two packed
// tanh.approx.f16x2 on pairs (i,g) and (f,o); gate arithmetic stays in half2
// (HFMA2 coefs, byte_perm half-swap + HMUL2 for ig*gg) so only 3 F2F
// conversions feed the f32 cell update. Cell tanh stays f32 MUFU.
// MUFU/lane-step: 3 -> floor 2.25*3*16 = 108 cyc/SMSP-step.
__global__ void __launch_bounds__(384, 1) lstm_kernel(
    const float* __restrict__ W_ih,   // [20,1]
    const float* __restrict__ W_hh,   // [20,5]
    const float* __restrict__ b_ih,   // [20]
    const float* __restrict__ b_hh,   // [20]
    const float* __restrict__ W_fc,   // [1,5]
    const float* __restrict__ b_fc,   // [1]
    float* __restrict__ out,          // [B,1]
    int B, int T)
{
    const int lane = threadIdx.x & 31;
    const int warpGlobal = (blockIdx.x * (blockDim.x >> 5)) + (threadIdx.x >> 5);
    const int grp  = lane / 5;                 // 0..6 (grp 6 = 2 leftover lanes)
    const int role = lane - grp * 5;           // 0..4 (unit index)
    const int base = grp * 5;                  // first lane of the group

    const int seqRaw = warpGlobal * 6 + grp;   // 6 real groups per warp
    const bool valid = (grp < 6) && (seqRaw < B);
    const int s = valid ? seqRaw : (B - 1);    // clamp: junk lanes do real math

    // Own unit u = role. Rows (PyTorch order): i=u, f=5+u, g=10+u, o=15+u.
    // sigmoid(z) = 0.5*tanh(z/2)+0.5 -> fold 0.5 into i,f,o rows; g row x1.
    // Pack z-pairs as (i,g) and (f,o) to match the f16x2 tanh pairing.
    ull wig, wfo, big, bfo, whhig[HID], whhfo[HID];
    {
        const int ri = role, rf = 5 + role, rg = 10 + role, ro = 15 + role;
        wig = pk2(W_ih[ri] * 0.5f, W_ih[rg]);
        wfo = pk2(W_ih[rf] * 0.5f, W_ih[ro] * 0.5f);
        big = pk2((b_ih[ri] + b_hh[ri]) * 0.5f, (b_ih[rg] + b_hh[rg]));
        bfo = pk2((b_ih[rf] + b_hh[rf]) * 0.5f, (b_ih[ro] + b_hh[ro]) * 0.5f);
        #pragma unroll
        for (int k = 0; k < HID; k++) {
            whhig[k] = pk2(W_hh[ri * HID + k] * 0.5f, W_hh[rg * HID + k]);
            whhfo[k] = pk2(W_hh[rf * HID + k] * 0.5f, W_hh[ro * HID + k] * 0.5f);
        }
    }

    // half2 gate coefficients: (i,g) -> a=(0.5,1.0) b=(0.5,0.0); (f,o) -> 0.5/0.5
    const __half2 cgA = __floats2half2_rn(0.5f, 1.0f);   // lo=0.5 (i), hi=1.0 (g)
    const __half2 cgB = __floats2half2_rn(0.5f, 0.0f);
    const __half2 cfA = __floats2half2_rn(0.5f, 0.5f);
    const __half2 cfB = __floats2half2_rn(0.5f, 0.5f);

    float h[HID];
    #pragma unroll
    for (int j = 0; j < HID; j++) h[j] = 0.0f;
    float cq = 0.0f;

    const int nblk = T / 8;
    const float4* xp0 = reinterpret_cast<const float4*>(g_xP);

    // prime first x block (5 lanes of a group read the same 32B -> broadcast)
    float4 xu = xp0[((size_t)0 * B + s) * 2 + 0];
    float4 xv = xp0[((size_t)0 * B + s) * 2 + 1];

    for (int tb = 0; tb < nblk; tb++) {
        const int tn = (tb + 1 < nblk) ? (tb + 1) : tb;
        const float4 un = xp0[((size_t)tn * B + s) * 2 + 0];
        const float4 vn = xp0[((size_t)tn * B + s) * 2 + 1];

        const float xs[8] = {xu.x, xu.y, xu.z, xu.w, xv.x, xv.y, xv.z, xv.w};

        #pragma unroll
        for (int kk = 0; kk < 8; kk++) {
            const float xval = xs[kk];
            const ull x2 = pk2(xval, xval);

            // z rows for the own unit, two partial chains to cut depth.
            ull zigA = fma2(x2, wig, big);
            ull zfoA = fma2(x2, wfo, bfo);
            {
                const ull h0 = pk2(h[0], h[0]);
                const ull h1 = pk2(h[1], h[1]);
                const ull h2 = pk2(h[2], h[2]);
                zigA = fma2(h0, whhig[0], zigA);
                zfoA = fma2(h0, whhfo[0], zfoA);
                zigA = fma2(h1, whhig[1], zigA);
                zfoA = fma2(h1, whhfo[1], zfoA);
                zigA = fma2(h2, whhig[2], zigA);
                zfoA = fma2(h2, whhfo[2], zfoA);
            }
            {
                const ull h3 = pk2(h[3], h[3]);
                const ull h4 = pk2(h[4], h[4]);
                ull zigB = fma2(h3, whhig[3], pk2(0.0f, 0.0f));
                ull zfoB = fma2(h3, whhfo[3], pk2(0.0f, 0.0f));
                zigB = fma2(h4, whhig[4], zigB);
                zfoB = fma2(h4, whhfo[4], zfoB);
                const ull ONE2 = pk2(1.0f, 1.0f);
                zigA = fma2(zigB, ONE2, zigA);
                zfoA = fma2(zfoB, ONE2, zfoA);
            }

            float zi, zg, zf, zo;
            upk2(zigA, zi, zg);
            upk2(zfoA, zf, zo);

            // packed gate path, arithmetic kept in half2:
            // (zi,zg): tanh -> HFMA2 coef -> (ig, gg); half-swap * self -> ig*gg
            const uint32_t tig = tanh_h2(cvt_h2(zg, zi));   // lo=t(zi), hi=t(zg)
            const __half2 igg = __hfma2(u2h2(tig), cgA, cgB);        // (ig, gg)
            const uint32_t iggu = *reinterpret_cast<const uint32_t*>(&igg);
            const __half2 swp = u2h2(__byte_perm(iggu, iggu, 0x1032)); // (gg, ig)
            const __half2 pr2 = __hmul2(igg, swp);          // both halves = ig*gg
            const float prod = __low2float(pr2);

            // (zf,zo): tanh -> HFMA2 -> (fg, og)
            const uint32_t tfo = tanh_h2(cvt_h2(zo, zf));   // lo=t(zf), hi=t(zo)
            const __half2 fog = __hfma2(u2h2(tfo), cfA, cfB);        // (fg, og)
            const float fg = __low2float(fog);
            const float og = __high2float(fog);

            cq = fmaf(fg, cq, prod);
            const float hq = og * fast_tanh(cq);

            // broadcast the 5 unit h-values within the group (independent shfls)
            h[0] = __shfl_sync(0xffffffffu, hq, base + 0);
            h[1] = __shfl_sync(0xffffffffu, hq, base + 1);
            h[2] = __shfl_sync(0xffffffffu, hq, base + 2);
            h[3] = __shfl_sync(0xffffffffu, hq, base + 3);
            h[4] = __shfl_sync(0xffffffffu, hq, base + 4);
        }

        xu = un; xv = vn;
    }

    // relu(h) @ W_fc^T + b_fc  (role-0 lane of each valid group writes)
    if (valid && role == 0) {
        float y = b_fc[0];
        #pragma unroll
        for (int j = 0; j < HID; j++) y = fmaf(fmaxf(h[j], 0.0f), W_fc[j], y);
        out[s] = y;
    }
}

extern "C" void kernel_launch(void* const* d_in, const int* in_sizes, int n_in,
                              void* d_out, int out_size) {
    const float* x    = (const float*)d_in[0];
    const float* W_ih = (const float*)d_in[1];
    const float* W_hh = (const float*)d_in[2];
    const float* b_ih = (const float*)d_in[3];
    const float* b_hh = (const float*)d_in[4];
    const float* W_fc = (const float*)d_in[5];
    const float* b_fc = (const float*)d_in[6];
    float* out = (float*)d_out;

    const int B = out_size;              // 8192
    const int T = in_sizes[0] / B;       // 2048

    const int npack = B * (T / 8);
    pack_kernel<<<(npack + 255) / 256, 256>>>(x, B, T);

    // Spread across ALL SMs: one block per SM (grid == SM count is load-
    // bearing). W = ceil(warps_needed / S) warps per block.
    int S = 0;
    cudaDeviceGetAttribute(&S, cudaDevAttrMultiProcessorCount, 0);
    if (S <= 0) S = 128;                 // defensive fallback
    const int warpsNeeded = (B + 5) / 6; // 1366 for B=8192
    int W = (warpsNeeded + S - 1) / S;   // 9 @ S=152, 10 @ S=148
    if (W > 12) W = 12;                  // cap at 384 threads (launch_bounds)
    const int threads = W * 32;
    const int blocks = S;
    lstm_kernel<<<blocks, threads>>>(W_ih, W_hh, b_ih, b_hh, W_fc, b_fc, out, B, T);
}

// round 15
// speedup vs baseline: 1.2911x; 1.2911x over previous
#include <cuda_runtime.h>
#include <cstdint>

// Problem constants: B=8192, T=2048, H=5, input dim 1.
#define MAX_B 8192
#define MAX_T 2048
#define HID 5

typedef unsigned long long ull;

// Packed x: xP[t/8][b][8] -> 32B per sequence per 8 steps, coalesced.
__device__ float g_xP[(size_t)MAX_T * MAX_B];

__device__ __forceinline__ float fast_tanh(float x) {
    float r;
    asm("tanh.approx.f32 %0, %1;" : "=f"(r) : "f"(x));
    return r;
}
__device__ __forceinline__ ull pk2(float lo, float hi) {
    ull r;
    asm("mov.b64 %0, {%1, %2};" : "=l"(r) : "f"(lo), "f"(hi));
    return r;
}
__device__ __forceinline__ void upk2(ull v, float& lo, float& hi) {
    asm("mov.b64 {%0, %1}, %2;" : "=f"(lo), "=f"(hi) : "l"(v));
}
// Packed fp32x2 FMA (sm_100+): one instruction = 2 fp32 FMAs.
__device__ __forceinline__ ull fma2(ull a, ull b, ull c) {
    ull r;
    asm("fma.rn.f32x2 %0, %1, %2, %3;" : "=l"(r) : "l"(a), "l"(b), "l"(c));
    return r;
}

// ---------------- pack: x[B,T] -> xP[T/8][B][8] ----------------
__global__ void pack_kernel(const float* __restrict__ x, int B, int T) {
    const int nblk = T / 8;
    int idx = blockIdx.x * blockDim.x + threadIdx.x;   // over B * nblk
    if (idx >= B * nblk) return;
    int b = idx / nblk;
    int k = idx - b * nblk;
    const float4* src = reinterpret_cast<const float4*>(x + (size_t)b * T + (size_t)k * 8);
    float4 u = src[0];
    float4 v = src[1];
    float4* dst = reinterpret_cast<float4*>(g_xP + ((size_t)k * B + b) * 8);
    dst[0] = u;
    dst[1] = v;
}

// ---------------- LSTM: mixed warp types, 2 warps/SMSP uniform -------------
// 8 warps/block on ALL S SMs -> every SMSP holds exactly 2 warps.
// A-type warp: 6 seqs x 5 lanes (lane = hidden unit), 5 tanh/warp-step.
// B-type warp: 8 seqs x 4 lanes (unit-ownership + shared unit 4), 7 tanh/step.
// nB_total = (B - 48*S)/2 warps are B-type (they carry 2 extra seqs each);
// at most one B-warp per SMSP -> binding SMSP = (5+7)*16 = 192 cyc/step
// (vs 240 for the 3-warp straggler SMSPs of the previous layout).
__global__ void __launch_bounds__(256, 1) lstm_kernel(
    const float* __restrict__ W_ih,   // [20,1]
    const float* __restrict__ W_hh,   // [20,5]
    const float* __restrict__ b_ih,   // [20]
    const float* __restrict__ b_hh,   // [20]
    const float* __restrict__ W_fc,   // [1,5]
    const float* __restrict__ b_fc,   // [1]
    float* __restrict__ out,          // [B,1]
    int B, int T)
{
    const int lane = threadIdx.x & 31;
    const int w    = threadIdx.x >> 5;       // warp id in block, 0..7
    const int S    = gridDim.x;

    // Partition: each block has aB B-type warps (warps 0..aB-1) and 8-aB A-type.
    int nBtot = B - 48 * S;
    nBtot = (nBtot > 0) ? (nBtot + 1) / 2 : 0;
    const int qq = nBtot / S, rr = nBtot - qq * S;
    const int aB = qq + ((blockIdx.x < rr) ? 1 : 0);
    const int cumB = (blockIdx.x < rr) ? blockIdx.x * (qq + 1)
                                       : rr * (qq + 1) + (blockIdx.x - rr) * qq;
    const int bbase = 48 * blockIdx.x + 2 * cumB;  // first seq of this block

    const int nblk = T / 8;
    const float4* xp0 = reinterpret_cast<const float4*>(g_xP);

    if (w < aB) {
        // ================= B-type: 8 seqs x 4 lanes (R6 scheme) =============
        const int q   = lane & 3;                  // lane role
        const int seqRaw = bbase + w * 8 + (lane >> 2);
        const bool valid = (seqRaw < B);
        const int s = valid ? seqRaw : (B - 1);

        ull wif, wgo, bif, bgo, whhif[HID], whhgo[HID];
        {
            const int ri = q, rf = 5 + q, rg = 10 + q, ro = 15 + q;
            wif = pk2(W_ih[ri] * 0.5f, W_ih[rf] * 0.5f);
            wgo = pk2(W_ih[rg],        W_ih[ro] * 0.5f);
            bif = pk2((b_ih[ri] + b_hh[ri]) * 0.5f, (b_ih[rf] + b_hh[rf]) * 0.5f);
            bgo = pk2((b_ih[rg] + b_hh[rg]),        (b_ih[ro] + b_hh[ro]) * 0.5f);
            #pragma unroll
            for (int k = 0; k < HID; k++) {
                whhif[k] = pk2(W_hh[ri * HID + k] * 0.5f, W_hh[rf * HID + k] * 0.5f);
                whhgo[k] = pk2(W_hh[rg * HID + k],        W_hh[ro * HID + k] * 0.5f);
            }
        }
        const int r4 = (q == 0) ? 4 : (q == 1) ? 14 : (q == 2) ? 9 : 19;
        const float s4 = (q == 1) ? 1.0f : 0.5f;
        const float a4 = s4;
        const float o4b = (q == 1) ? 0.0f : 0.5f;
        float w4 = W_ih[r4] * s4;
        float b4 = (b_ih[r4] + b_hh[r4]) * s4;
        float whh4[HID];
        #pragma unroll
        for (int k = 0; k < HID; k++) whh4[k] = W_hh[r4 * HID + k] * s4;

        const bool selHi = (q & 2) != 0;
        const bool selLo = (q & 1) != 0;

        float h[HID];
        #pragma unroll
        for (int j = 0; j < HID; j++) h[j] = 0.0f;
        float cq = 0.0f, c4 = 0.0f;

        float4 xu = xp0[((size_t)0 * B + s) * 2 + 0];
        float4 xv = xp0[((size_t)0 * B + s) * 2 + 1];

        for (int tb = 0; tb < nblk; tb++) {
            const int tn = (tb + 1 < nblk) ? (tb + 1) : tb;
            const float4 un = xp0[((size_t)tn * B + s) * 2 + 0];
            const float4 vn = xp0[((size_t)tn * B + s) * 2 + 1];
            const float xs[8] = {xu.x, xu.y, xu.z, xu.w, xv.x, xv.y, xv.z, xv.w};

            #pragma unroll
            for (int kk = 0; kk < 8; kk++) {
                const float xval = xs[kk];
                const ull x2 = pk2(xval, xval);

                ull zif = fma2(x2, wif, bif);
                ull zgo = fma2(x2, wgo, bgo);
                float z4 = fmaf(xval, w4, b4);
                #pragma unroll
                for (int k = 0; k < HID; k++) {
                    const ull h2 = pk2(h[k], h[k]);
                    zif = fma2(h2, whhif[k], zif);
                    zgo = fma2(h2, whhgo[k], zgo);
                    z4 = fmaf(h[k], whh4[k], z4);
                }

                float zi, zf, zg, zo;
                upk2(zif, zi, zf);
                upk2(zgo, zg, zo);

                const float ig = fmaf(0.5f, fast_tanh(zi), 0.5f);
                const float fg = fmaf(0.5f, fast_tanh(zf), 0.5f);
                const float gg = fast_tanh(zg);
                const float og = fmaf(0.5f, fast_tanh(zo), 0.5f);
                cq = fmaf(fg, cq, ig * gg);
                const float hq = og * fast_tanh(cq);

                const float v4 = fmaf(a4, fast_tanh(z4), o4b);
                const float rA = __shfl_xor_sync(0xffffffffu, v4, 1);
                const float p  = v4 * rA;
                const float px = __shfl_xor_sync(0xffffffffu, p, 2);
                const float P  = selHi ? px : p;
                const float rB = __shfl_xor_sync(0xffffffffu, v4, 2);
                const float rC = __shfl_xor_sync(0xffffffffu, rB, 1);
                const float F4 = selHi ? (selLo ? rA : v4) : (selLo ? rC : rB);
                const float O4 = selHi ? (selLo ? v4 : rA) : (selLo ? rB : rC);
                c4 = fmaf(F4, c4, P);
                const float h4 = O4 * fast_tanh(c4);

                h[0] = __shfl_sync(0xffffffffu, hq, 0, 4);
                h[1] = __shfl_sync(0xffffffffu, hq, 1, 4);
                h[2] = __shfl_sync(0xffffffffu, hq, 2, 4);
                h[3] = __shfl_sync(0xffffffffu, hq, 3, 4);
                h[4] = h4;
            }
            xu = un; xv = vn;
        }

        if (valid && q == 0) {
            float y = b_fc[0];
            #pragma unroll
            for (int j = 0; j < HID; j++) y = fmaf(fmaxf(h[j], 0.0f), W_fc[j], y);
            out[s] = y;
        }
    } else {
        // ================= A-type: 6 seqs x 5 lanes (R13 scheme) ============
        const int grp  = lane / 5;                 // 0..6
        const int role = lane - grp * 5;           // 0..4
        const int base = grp * 5;

        const int seqRaw = bbase + aB * 8 + (w - aB) * 6 + grp;
        const bool valid = (grp < 6) && (seqRaw < B);
        const int s = valid ? seqRaw : (B - 1);

        ull wif, wgo, bif, bgo, whhif[HID], whhgo[HID];
        {
            const int ri = role, rf = 5 + role, rg = 10 + role, ro = 15 + role;
            wif = pk2(W_ih[ri] * 0.5f, W_ih[rf] * 0.5f);
            wgo = pk2(W_ih[rg],        W_ih[ro] * 0.5f);
            bif = pk2((b_ih[ri] + b_hh[ri]) * 0.5f, (b_ih[rf] + b_hh[rf]) * 0.5f);
            bgo = pk2((b_ih[rg] + b_hh[rg]),        (b_ih[ro] + b_hh[ro]) * 0.5f);
            #pragma unroll
            for (int k = 0; k < HID; k++) {
                whhif[k] = pk2(W_hh[ri * HID + k] * 0.5f, W_hh[rf * HID + k] * 0.5f);
                whhgo[k] = pk2(W_hh[rg * HID + k],        W_hh[ro * HID + k] * 0.5f);
            }
        }

        float h[HID];
        #pragma unroll
        for (int j = 0; j < HID; j++) h[j] = 0.0f;
        float cq = 0.0f;

        float4 xu = xp0[((size_t)0 * B + s) * 2 + 0];
        float4 xv = xp0[((size_t)0 * B + s) * 2 + 1];

        for (int tb = 0; tb < nblk; tb++) {
            const int tn = (tb + 1 < nblk) ? (tb + 1) : tb;
            const float4 un = xp0[((size_t)tn * B + s) * 2 + 0];
            const float4 vn = xp0[((size_t)tn * B + s) * 2 + 1];
            const float xs[8] = {xu.x, xu.y, xu.z, xu.w, xv.x, xv.y, xv.z, xv.w};

            #pragma unroll
            for (int kk = 0; kk < 8; kk++) {
                const float xval = xs[kk];
                const ull x2 = pk2(xval, xval);

                ull zifA = fma2(x2, wif, bif);
                ull zgoA = fma2(x2, wgo, bgo);
                {
                    const ull h0 = pk2(h[0], h[0]);
                    const ull h1 = pk2(h[1], h[1]);
                    const ull h2 = pk2(h[2], h[2]);
                    zifA = fma2(h0, whhif[0], zifA);
                    zgoA = fma2(h0, whhgo[0], zgoA);
                    zifA = fma2(h1, whhif[1], zifA);
                    zgoA = fma2(h1, whhgo[1], zgoA);
                    zifA = fma2(h2, whhif[2], zifA);
                    zgoA = fma2(h2, whhgo[2], zgoA);
                }
                {
                    const ull h3 = pk2(h[3], h[3]);
                    const ull h4 = pk2(h[4], h[4]);
                    ull zifB = fma2(h3, whhif[3], pk2(0.0f, 0.0f));
                    ull zgoB = fma2(h3, whhgo[3], pk2(0.0f, 0.0f));
                    zifB = fma2(h4, whhif[4], zifB);
                    zgoB = fma2(h4, whhgo[4], zgoB);
                    const ull ONE2 = pk2(1.0f, 1.0f);
                    zifA = fma2(zifB, ONE2, zifA);
                    zgoA = fma2(zgoB, ONE2, zgoA);
                }

                float zi, zf, zg, zo;
                upk2(zifA, zi, zf);
                upk2(zgoA, zg, zo);

                const float ig = fmaf(0.5f, fast_tanh(zi), 0.5f);
                const float fg = fmaf(0.5f, fast_tanh(zf), 0.5f);
                const float gg = fast_tanh(zg);
                const float og = fmaf(0.5f, fast_tanh(zo), 0.5f);
                cq = fmaf(fg, cq, ig * gg);
                const float hq = og * fast_tanh(cq);

                h[0] = __shfl_sync(0xffffffffu, hq, base + 0);
                h[1] = __shfl_sync(0xffffffffu, hq, base + 1);
                h[2] = __shfl_sync(0xffffffffu, hq, base + 2);
                h[3] = __shfl_sync(0xffffffffu, hq, base + 3);
                h[4] = __shfl_sync(0xffffffffu, hq, base + 4);
            }
            xu = un; xv = vn;
        }

        if (valid && role == 0) {
            float y = b_fc[0];
            #pragma unroll
            for (int j = 0; j < HID; j++) y = fmaf(fmaxf(h[j], 0.0f), W_fc[j], y);
            out[s] = y;
        }
    }
}

extern "C" void kernel_launch(void* const* d_in, const int* in_sizes, int n_in,
                              void* d_out, int out_size) {
    const float* x    = (const float*)d_in[0];
    const float* W_ih = (const float*)d_in[1];
    const float* W_hh = (const float*)d_in[2];
    const float* b_ih = (const float*)d_in[3];
    const float* b_hh = (const float*)d_in[4];
    const float* W_fc = (const float*)d_in[5];
    const float* b_fc = (const float*)d_in[6];
    float* out = (float*)d_out;

    const int B = out_size;              // 8192
    const int T = in_sizes[0] / B;       // 2048

    const int npack = B * (T / 8);
    pack_kernel<<<(npack + 255) / 256, 256>>>(x, B, T);

    // 8 warps/block on every SM -> exactly 2 warps per SMSP chip-wide.
    // B-type warps (8 seqs) absorb the seqs that 6-seq A-warps can't cover.
    int S = 0;
    cudaDeviceGetAttribute(&S, cudaDevAttrMultiProcessorCount, 0);
    if (S <= 0) S = 128;                 // defensive fallback
    lstm_kernel<<<S, 256>>>(W_ih, W_hh, b_ih, b_hh, W_fc, b_fc, out, B, T);
}